// round 5
// baseline (speedup 1.0000x reference)
#include <cuda_runtime.h>

#define BB 2048
#define CC 1024
#define FF 128
#define NIT 10

// Scratch (no allocs allowed -> device globals)
__device__ float g_M[BB*CC];                 // dot matrix: M[b][j] = ue_b . item_emb[j]
__device__ float g_K[BB*CC];                 // K = exp(affinity/eps)
__device__ float g_u[BB];
__device__ float g_colsum[(NIT+1)*CC];       // colsum[i] = K^T u_i, i=1..10
__device__ float g_sumD;

// ---------------- zero accumulators ----------------
__global__ void k_zero() {
    int i = blockIdx.x*blockDim.x + threadIdx.x;
    int n = (NIT+1)*CC;
    for (; i < n; i += gridDim.x*blockDim.x) g_colsum[i] = 0.f;
    if (blockIdx.x == 0 && threadIdx.x == 0) g_sumD = 0.f;
}

// ---------------- sum(D) ----------------
__global__ void k_sumD(const float* __restrict__ D) {
    __shared__ float sm[256];
    int t = threadIdx.x;
    float s = 0.f;
    int n4 = BB*CC/4;
    for (int i = blockIdx.x*256 + t; i < n4; i += gridDim.x*256) {
        float4 v = ((const float4*)D)[i];
        s += (v.x+v.y)+(v.z+v.w);
    }
    sm[t] = s; __syncthreads();
    for (int o = 128; o > 0; o >>= 1) { if (t < o) sm[t] += sm[t+o]; __syncthreads(); }
    if (t == 0) atomicAdd(&g_sumD, sm[0]);
}

// ---------------- GEMM: M = UE @ IE^T  (both K-major, NT) ----------------
// block: 64x64 tile, 256 threads, 4x4 microtile, K=128 in two 64-chunks
__global__ void k_gemm(const int* __restrict__ users,
                       const float* __restrict__ item_emb,
                       const float* __restrict__ user_emb) {
    __shared__ float As[64][64];   // [k][row]
    __shared__ float Bs[64][64];   // [k][col]
    __shared__ int   ur[64];
    int t  = threadIdx.x;
    int tx = t & 15, ty = t >> 4;
    int r0 = blockIdx.y * 64, c0 = blockIdx.x * 64;
    if (t < 64) ur[t] = users[r0 + t];
    __syncthreads();

    float acc[4][4];
    #pragma unroll
    for (int i = 0; i < 4; i++)
        #pragma unroll
        for (int j = 0; j < 4; j++) acc[i][j] = 0.f;

    for (int kk = 0; kk < FF; kk += 64) {
        #pragma unroll
        for (int l = 0; l < 4; l++) {
            int idx = t + l*256;
            int row = idx & 63, kq = idx >> 6;   // kq: 0..15
            float4 va = *(const float4*)&user_emb[(size_t)ur[row]*FF + kk + kq*4];
            As[kq*4+0][row] = va.x; As[kq*4+1][row] = va.y;
            As[kq*4+2][row] = va.z; As[kq*4+3][row] = va.w;
            float4 vb = *(const float4*)&item_emb[(size_t)(c0+row)*FF + kk + kq*4];
            Bs[kq*4+0][row] = vb.x; Bs[kq*4+1][row] = vb.y;
            Bs[kq*4+2][row] = vb.z; Bs[kq*4+3][row] = vb.w;
        }
        __syncthreads();
        #pragma unroll
        for (int k = 0; k < 64; k++) {
            float4 a = *(float4*)&As[k][ty*4];
            float4 b = *(float4*)&Bs[k][tx*4];
            acc[0][0] += a.x*b.x; acc[0][1] += a.x*b.y; acc[0][2] += a.x*b.z; acc[0][3] += a.x*b.w;
            acc[1][0] += a.y*b.x; acc[1][1] += a.y*b.y; acc[1][2] += a.y*b.z; acc[1][3] += a.y*b.w;
            acc[2][0] += a.z*b.x; acc[2][1] += a.z*b.y; acc[2][2] += a.z*b.z; acc[2][3] += a.z*b.w;
            acc[3][0] += a.w*b.x; acc[3][1] += a.w*b.y; acc[3][2] += a.w*b.z; acc[3][3] += a.w*b.w;
        }
        __syncthreads();
    }
    #pragma unroll
    for (int i = 0; i < 4; i++) {
        float4 o = make_float4(acc[i][0], acc[i][1], acc[i][2], acc[i][3]);
        *(float4*)&g_M[(size_t)(r0 + ty*4 + i)*CC + c0 + tx*4] = o;
    }
}

// ---------------- F1: build K, u1 (v=1), colsum1 partials ----------------
// block = 8 rows, 256 threads; thread t owns columns 4t..4t+3
__global__ void k_F1(const int* __restrict__ items, const float* __restrict__ D) {
    __shared__ float mrow[CC];
    __shared__ float rs[8][256];
    __shared__ float su[8];
    int t  = threadIdx.x;
    int b0 = blockIdx.x * 8;
    float inv_mean = (float)(BB*CC) / g_sumD;   // D/mean = D*inv_mean
    float4 kv[8];
    #pragma unroll
    for (int r = 0; r < 8; r++) {
        int b = b0 + r;
        ((float4*)mrow)[t] = ((const float4*)g_M)[b*256 + t];
        __syncthreads();
        int4   it = ((const int4*)items)[b*256 + t];
        float4 d  = ((const float4*)D)[b*256 + t];
        float4 k;
        k.x = __expf(5.f*(mrow[it.x] - d.x*inv_mean));
        k.y = __expf(5.f*(mrow[it.y] - d.y*inv_mean));
        k.z = __expf(5.f*(mrow[it.z] - d.z*inv_mean));
        k.w = __expf(5.f*(mrow[it.w] - d.w*inv_mean));
        ((float4*)g_K)[b*256 + t] = k;
        kv[r] = k;
        rs[r][t] = (k.x+k.y)+(k.z+k.w);
        __syncthreads();
    }
    // reduce rowsums: warp w handles row w
    int w = t >> 5, l = t & 31;
    {
        float s = 0.f;
        #pragma unroll
        for (int j = 0; j < 8; j++) s += rs[w][l + j*32];
        #pragma unroll
        for (int o = 16; o > 0; o >>= 1) s += __shfl_down_sync(0xffffffffu, s, o);
        if (l == 0) { float u = 1.f/s; su[w] = u; g_u[b0+w] = u; }
    }
    __syncthreads();
    float4 acc = make_float4(0.f,0.f,0.f,0.f);
    #pragma unroll
    for (int r = 0; r < 8; r++) {
        float u = su[r];
        acc.x += kv[r].x*u; acc.y += kv[r].y*u;
        acc.z += kv[r].z*u; acc.w += kv[r].w*u;
    }
    float* cs = g_colsum + 1*CC;
    atomicAdd(&cs[4*t+0], acc.x);
    atomicAdd(&cs[4*t+1], acc.y);
    atomicAdd(&cs[4*t+2], acc.z);
    atomicAdd(&cs[4*t+3], acc.w);
}

// ---------------- F_it (it=2..10): v_{it-1}, u_it, colsum_it partials ----------------
__global__ void k_Fiter(const float* __restrict__ capacities, int it) {
    __shared__ float rs[8][256];
    __shared__ float su[8];
    int t  = threadIdx.x;
    int b0 = blockIdx.x * 8;
    const float scaling = (float)BB / 100000.0f;
    float4 cs  = ((const float4*)(g_colsum + (it-1)*CC))[t];
    float4 cap = ((const float4*)capacities)[t];
    float4 vv;
    vv.x = cap.x*scaling/cs.x; vv.y = cap.y*scaling/cs.y;
    vv.z = cap.z*scaling/cs.z; vv.w = cap.w*scaling/cs.w;
    float4 kv[8];
    #pragma unroll
    for (int r = 0; r < 8; r++) {
        kv[r] = ((const float4*)g_K)[(b0+r)*256 + t];
        rs[r][t] = (kv[r].x*vv.x + kv[r].y*vv.y) + (kv[r].z*vv.z + kv[r].w*vv.w);
    }
    __syncthreads();
    int w = t >> 5, l = t & 31;
    {
        float s = 0.f;
        #pragma unroll
        for (int j = 0; j < 8; j++) s += rs[w][l + j*32];
        #pragma unroll
        for (int o = 16; o > 0; o >>= 1) s += __shfl_down_sync(0xffffffffu, s, o);
        if (l == 0) { float u = 1.f/s; su[w] = u; g_u[b0+w] = u; }
    }
    __syncthreads();
    float4 acc = make_float4(0.f,0.f,0.f,0.f);
    #pragma unroll
    for (int r = 0; r < 8; r++) {
        float u = su[r];
        acc.x += kv[r].x*u; acc.y += kv[r].y*u;
        acc.z += kv[r].z*u; acc.w += kv[r].w*u;
    }
    float* csw = g_colsum + it*CC;
    atomicAdd(&csw[4*t+0], acc.x);
    atomicAdd(&csw[4*t+1], acc.y);
    atomicAdd(&csw[4*t+2], acc.z);
    atomicAdd(&csw[4*t+3], acc.w);
}

// ---------------- final: v10 + P = K * u10 (x) v10 ----------------
__global__ void k_final(const float* __restrict__ capacities, float* __restrict__ out) {
    int t  = threadIdx.x;
    int b0 = blockIdx.x * 8;
    const float scaling = (float)BB / 100000.0f;
    float4 cs  = ((const float4*)(g_colsum + NIT*CC))[t];
    float4 cap = ((const float4*)capacities)[t];
    float4 vv;
    vv.x = cap.x*scaling/cs.x; vv.y = cap.y*scaling/cs.y;
    vv.z = cap.z*scaling/cs.z; vv.w = cap.w*scaling/cs.w;
    #pragma unroll
    for (int r = 0; r < 8; r++) {
        int b = b0 + r;
        float u = g_u[b];
        float4 k = ((const float4*)g_K)[b*256 + t];
        float4 p;
        p.x = k.x*u*vv.x; p.y = k.y*u*vv.y;
        p.z = k.z*u*vv.z; p.w = k.w*u*vv.w;
        ((float4*)out)[b*256 + t] = p;
    }
}

extern "C" void kernel_launch(void* const* d_in, const int* in_sizes, int n_in,
                              void* d_out, int out_size) {
    const int*   users      = (const int*)  d_in[0];
    const int*   items      = (const int*)  d_in[1];
    const float* D          = (const float*)d_in[2];
    const float* capacities = (const float*)d_in[3];
    const float* item_emb   = (const float*)d_in[4];
    const float* user_emb   = (const float*)d_in[5];
    float* out = (float*)d_out;

    k_zero<<<32, 256>>>();
    k_sumD<<<148, 256>>>(D);
    k_gemm<<<dim3(CC/64, BB/64), 256>>>(users, item_emb, user_emb);
    k_F1<<<BB/8, 256>>>(items, D);
    for (int it = 2; it <= NIT; it++)
        k_Fiter<<<BB/8, 256>>>(capacities, it);
    k_final<<<BB/8, 256>>>(capacities, out);
}

// round 6
// speedup vs baseline: 1.8953x; 1.8953x over previous
#include <cuda_runtime.h>

#define BB 2048
#define CC 1024
#define FF 128
#define NIT 10
#define NBLK (BB/8)          // 256 blocks, must all be co-resident

// Scratch (no allocs allowed -> device globals)
__device__ float    g_M[BB*CC];               // dot matrix: M[b][j] = ue_b . item_emb[j]
__device__ float    g_cs[NIT+1][8][CC];       // banked colsum partials per iteration
__device__ float    g_sumD;
__device__ unsigned g_bar[16];                // one-shot grid-barrier counters

// ---------------- zero accumulators / barrier counters ----------------
__global__ void k_zero() {
    int i = blockIdx.x*blockDim.x + threadIdx.x;
    int n = (NIT+1)*8*CC;
    float* cs = &g_cs[0][0][0];
    for (; i < n; i += gridDim.x*blockDim.x) cs[i] = 0.f;
    if (blockIdx.x == 0 && threadIdx.x < 16) g_bar[threadIdx.x] = 0u;
    if (blockIdx.x == 0 && threadIdx.x == 0) g_sumD = 0.f;
}

// ---------------- sum(D) ----------------
__global__ void k_sumD(const float* __restrict__ D) {
    __shared__ float sm[256];
    int t = threadIdx.x;
    float s = 0.f;
    int n4 = BB*CC/4;
    for (int i = blockIdx.x*256 + t; i < n4; i += gridDim.x*256) {
        float4 v = ((const float4*)D)[i];
        s += (v.x+v.y)+(v.z+v.w);
    }
    sm[t] = s; __syncthreads();
    for (int o = 128; o > 0; o >>= 1) { if (t < o) sm[t] += sm[t+o]; __syncthreads(); }
    if (t == 0) atomicAdd(&g_sumD, sm[0]);
}

// ---------------- GEMM: M = UE @ IE^T  (both K-major, NT) ----------------
__global__ void k_gemm(const int* __restrict__ users,
                       const float* __restrict__ item_emb,
                       const float* __restrict__ user_emb) {
    __shared__ float As[64][64];   // [k][row]
    __shared__ float Bs[64][64];   // [k][col]
    __shared__ int   ur[64];
    int t  = threadIdx.x;
    int tx = t & 15, ty = t >> 4;
    int r0 = blockIdx.y * 64, c0 = blockIdx.x * 64;
    if (t < 64) ur[t] = users[r0 + t];
    __syncthreads();

    float acc[4][4];
    #pragma unroll
    for (int i = 0; i < 4; i++)
        #pragma unroll
        for (int j = 0; j < 4; j++) acc[i][j] = 0.f;

    for (int kk = 0; kk < FF; kk += 64) {
        #pragma unroll
        for (int l = 0; l < 4; l++) {
            int idx = t + l*256;
            int row = idx & 63, kq = idx >> 6;
            float4 va = *(const float4*)&user_emb[(size_t)ur[row]*FF + kk + kq*4];
            As[kq*4+0][row] = va.x; As[kq*4+1][row] = va.y;
            As[kq*4+2][row] = va.z; As[kq*4+3][row] = va.w;
            float4 vb = *(const float4*)&item_emb[(size_t)(c0+row)*FF + kk + kq*4];
            Bs[kq*4+0][row] = vb.x; Bs[kq*4+1][row] = vb.y;
            Bs[kq*4+2][row] = vb.z; Bs[kq*4+3][row] = vb.w;
        }
        __syncthreads();
        #pragma unroll
        for (int k = 0; k < 64; k++) {
            float4 a = *(float4*)&As[k][ty*4];
            float4 b = *(float4*)&Bs[k][tx*4];
            acc[0][0] += a.x*b.x; acc[0][1] += a.x*b.y; acc[0][2] += a.x*b.z; acc[0][3] += a.x*b.w;
            acc[1][0] += a.y*b.x; acc[1][1] += a.y*b.y; acc[1][2] += a.y*b.z; acc[1][3] += a.y*b.w;
            acc[2][0] += a.z*b.x; acc[2][1] += a.z*b.y; acc[2][2] += a.z*b.z; acc[2][3] += a.z*b.w;
            acc[3][0] += a.w*b.x; acc[3][1] += a.w*b.y; acc[3][2] += a.w*b.z; acc[3][3] += a.w*b.w;
        }
        __syncthreads();
    }
    #pragma unroll
    for (int i = 0; i < 4; i++) {
        float4 o = make_float4(acc[i][0], acc[i][1], acc[i][2], acc[i][3]);
        *(float4*)&g_M[(size_t)(r0 + ty*4 + i)*CC + c0 + tx*4] = o;
    }
}

// ---------------- grid-wide barrier (all NBLK blocks co-resident) ----------------
__device__ __forceinline__ void grid_barrier(int id) {
    __syncthreads();
    if (threadIdx.x == 0) {
        __threadfence();
        unsigned arrived = atomicAdd(&g_bar[id], 1u) + 1u;
        if (arrived < (unsigned)NBLK) {
            volatile unsigned* p = &g_bar[id];
            while (*p < (unsigned)NBLK) { }
        }
        __threadfence();
    }
    __syncthreads();
}

// ---------------- fused Sinkhorn: K build + 10 iterations + P write ----------------
// block = 8 rows (full width), thread t owns columns 4t..4t+3; K lives in kv[8] regs.
__global__ void __launch_bounds__(256, 2)
k_sink(const int* __restrict__ items, const float* __restrict__ D,
       const float* __restrict__ capacities, float* __restrict__ out) {
    __shared__ float mrows[8][CC];   // 32 KB
    __shared__ float rs[8][256];     // 8 KB
    __shared__ float su[8];
    int t   = threadIdx.x;
    int bid = blockIdx.x;
    int b0  = bid * 8;
    int sb  = bid & 7;               // which partial-colsum bank we write
    int w = t >> 5, l = t & 31;

    // ---- stage all 8 M rows at once (coalesced, MLP=8) ----
    #pragma unroll
    for (int r = 0; r < 8; r++)
        ((float4*)mrows[r])[t] = ((const float4*)g_M)[(b0 + r)*256 + t];
    float inv_mean = (float)(BB*CC) / g_sumD;
    __syncthreads();

    // ---- build K in registers, rowsum with v=1 ----
    float4 kv[8];
    #pragma unroll
    for (int r = 0; r < 8; r++) {
        int b = b0 + r;
        int4   it4 = ((const int4*)items)[b*256 + t];
        float4 d   = ((const float4*)D)[b*256 + t];
        float4 k;
        k.x = __expf(5.f*(mrows[r][it4.x] - d.x*inv_mean));
        k.y = __expf(5.f*(mrows[r][it4.y] - d.y*inv_mean));
        k.z = __expf(5.f*(mrows[r][it4.z] - d.z*inv_mean));
        k.w = __expf(5.f*(mrows[r][it4.w] - d.w*inv_mean));
        kv[r] = k;
        rs[r][t] = (k.x + k.y) + (k.z + k.w);
    }
    __syncthreads();
    // rowsum reduce: warp w handles row w
    {
        float s = 0.f;
        #pragma unroll
        for (int j = 0; j < 8; j++) s += rs[w][l + j*32];
        #pragma unroll
        for (int o = 16; o > 0; o >>= 1) s += __shfl_down_sync(0xffffffffu, s, o);
        if (l == 0) su[w] = 1.f / s;
    }
    __syncthreads();
    // colsum partials for it=1
    {
        float4 acc = make_float4(0.f, 0.f, 0.f, 0.f);
        #pragma unroll
        for (int r = 0; r < 8; r++) {
            float u = su[r];
            acc.x += kv[r].x*u; acc.y += kv[r].y*u;
            acc.z += kv[r].z*u; acc.w += kv[r].w*u;
        }
        float* cs = &g_cs[1][sb][0];
        atomicAdd(&cs[4*t+0], acc.x);
        atomicAdd(&cs[4*t+1], acc.y);
        atomicAdd(&cs[4*t+2], acc.z);
        atomicAdd(&cs[4*t+3], acc.w);
    }
    grid_barrier(1);

    const float scaling = (float)BB / 100000.0f;
    float4 cap = ((const float4*)capacities)[t];

    // ---- iterations 2..10, K stays in registers ----
    for (int it = 2; it <= NIT; it++) {
        // v_{it-1} from banked colsum partials (each address read once per launch)
        float4 c = make_float4(0.f, 0.f, 0.f, 0.f);
        #pragma unroll
        for (int s8 = 0; s8 < 8; s8++) {
            float4 p = ((const float4*)g_cs[it-1][s8])[t];
            c.x += p.x; c.y += p.y; c.z += p.z; c.w += p.w;
        }
        float4 vv;
        vv.x = cap.x*scaling/c.x; vv.y = cap.y*scaling/c.y;
        vv.z = cap.z*scaling/c.z; vv.w = cap.w*scaling/c.w;

        #pragma unroll
        for (int r = 0; r < 8; r++)
            rs[r][t] = (kv[r].x*vv.x + kv[r].y*vv.y) + (kv[r].z*vv.z + kv[r].w*vv.w);
        __syncthreads();
        {
            float s = 0.f;
            #pragma unroll
            for (int j = 0; j < 8; j++) s += rs[w][l + j*32];
            #pragma unroll
            for (int o = 16; o > 0; o >>= 1) s += __shfl_down_sync(0xffffffffu, s, o);
            if (l == 0) su[w] = 1.f / s;
        }
        __syncthreads();
        float4 acc = make_float4(0.f, 0.f, 0.f, 0.f);
        #pragma unroll
        for (int r = 0; r < 8; r++) {
            float u = su[r];
            acc.x += kv[r].x*u; acc.y += kv[r].y*u;
            acc.z += kv[r].z*u; acc.w += kv[r].w*u;
        }
        float* csw = &g_cs[it][sb][0];
        atomicAdd(&csw[4*t+0], acc.x);
        atomicAdd(&csw[4*t+1], acc.y);
        atomicAdd(&csw[4*t+2], acc.z);
        atomicAdd(&csw[4*t+3], acc.w);
        grid_barrier(it);
    }

    // ---- final: v10, P = K * u10 (x) v10 ----
    {
        float4 c = make_float4(0.f, 0.f, 0.f, 0.f);
        #pragma unroll
        for (int s8 = 0; s8 < 8; s8++) {
            float4 p = ((const float4*)g_cs[NIT][s8])[t];
            c.x += p.x; c.y += p.y; c.z += p.z; c.w += p.w;
        }
        float4 vv;
        vv.x = cap.x*scaling/c.x; vv.y = cap.y*scaling/c.y;
        vv.z = cap.z*scaling/c.z; vv.w = cap.w*scaling/c.w;
        #pragma unroll
        for (int r = 0; r < 8; r++) {
            int b = b0 + r;
            float u = su[r];
            float4 p;
            p.x = kv[r].x*u*vv.x; p.y = kv[r].y*u*vv.y;
            p.z = kv[r].z*u*vv.z; p.w = kv[r].w*u*vv.w;
            ((float4*)out)[b*256 + t] = p;
        }
    }
}

extern "C" void kernel_launch(void* const* d_in, const int* in_sizes, int n_in,
                              void* d_out, int out_size) {
    const int*   users      = (const int*)  d_in[0];
    const int*   items      = (const int*)  d_in[1];
    const float* D          = (const float*)d_in[2];
    const float* capacities = (const float*)d_in[3];
    const float* item_emb   = (const float*)d_in[4];
    const float* user_emb   = (const float*)d_in[5];
    float* out = (float*)d_out;

    k_zero<<<96, 256>>>();
    k_sumD<<<148, 256>>>(D);
    k_gemm<<<dim3(CC/64, BB/64), 256>>>(users, item_emb, user_emb);
    k_sink<<<NBLK, 256>>>(items, D, capacities, out);
}